// round 11
// baseline (speedup 1.0000x reference)
#include <cuda_runtime.h>
#include <cstdint>
#include <math.h>

// bayes_55018531062578  (R11: R6 structure + pipe-balanced threefry rounds)
//
// out[b] = sigmoid( BEVb[b]-BEVa[b] + (sum_{s<kapa} B[b,k*,s] - A[b,k*,s]) / kapa[b] )
// k*(b,s) = argmax_k ( log_softmax(mean)_k + gumbel(b,s,k) )
// gumbel: JAX partitionable threefry counter mode, bits = o0^o1 of
//   threefry2x32(key=(0,42), (0, i)),  u = bitcast((bits>>9)|0x3f800000)-1
// Fast argmax == argmin_k t_k * (1/w_k),  t_k = -log2(u_k); near-tie
// fallback replays reference formula (with eps) in accurate fp32.
//
// Pipe balancing: rounds with rotations {17,29,16,24} compute
//   x1 = ((x1*2^r)_lo | (x1*2^r)_hi) ^ x0
// as IMAD + IMAD.HI (fma pipe) + one fused LOP3(0x56) (alu), instead of
// SHF + LOP3 (both alu). Multipliers are runtime kernel args so ptxas
// cannot strength-reduce the muls back into shifts. Moves ~80 instrs/sample
// from the saturated alu pipe (70%) to the idle fma pipe (22%).

#define EPSF 1e-20f

__device__ __forceinline__ uint32_t rotl32(uint32_t x, int r) {
    return __funnelshift_l(x, x, r);
}

// x1 = rotl(x1, r) ^ x0 with rotation on the FMA pipe:
//   lo = x1 * m (m = 1<<r, runtime), hi = mulhi(x1, m), result = (lo|hi)^x0
__device__ __forceinline__ uint32_t rotxor_imad(uint32_t x1, uint32_t m, uint32_t x0) {
    uint32_t lo, hi, res;
    asm("mul.lo.u32 %0, %1, %2;" : "=r"(lo) : "r"(x1), "r"(m));
    asm("mul.hi.u32 %0, %1, %2;" : "=r"(hi) : "r"(x1), "r"(m));
    asm("lop3.b32 %0, %1, %2, %3, 0x56;" : "=r"(res) : "r"(lo), "r"(hi), "r"(x0));
    return res;
}

// threefry2x32, key (0,42), input (0, ctr); returns o0 ^ o1.
// m17/m29/m16/m24 = 1<<17, 1<<29, 1<<16, 1<<24 (runtime).
__device__ __forceinline__ uint32_t threefry_xor(uint32_t ctr,
                                                 uint32_t m17, uint32_t m29,
                                                 uint32_t m16, uint32_t m24) {
    const uint32_t ks0 = 0u;
    const uint32_t ks1 = 42u;
    const uint32_t ks2 = 0x1BD11BDAu ^ 42u;

    uint32_t x0 = ks0;
    uint32_t x1 = ctr + ks1;

    // group rotations {13,15,26,6}: SHF path (alu)
#define TF_SHF(r)  { x0 += x1; x1 = rotl32(x1,(r)) ^ x0; }
    // group rotations {17,29,16,24}: IMAD path (fma)
#define TF_IMAD(m) { x0 += x1; x1 = rotxor_imad(x1, (m), x0); }

#define TF4A  TF_SHF(13) TF_SHF(15) TF_SHF(26) TF_SHF(6)
#define TF4B  TF_IMAD(m17) TF_IMAD(m29) TF_IMAD(m16) TF_IMAD(m24)

    TF4A  x0 += ks1; x1 += ks2 + 1u;
    TF4B  x0 += ks2; x1 += ks0 + 2u;
    TF4A  x0 += ks0; x1 += ks1 + 3u;
    TF4B  x0 += ks1; x1 += ks2 + 4u;
    TF4A  x0 += ks2; x1 += ks0 + 5u;

#undef TF4A
#undef TF4B
#undef TF_SHF
#undef TF_IMAD
    return x0 ^ x1;
}

__device__ __forceinline__ float bits_to_uniform(uint32_t bits) {
    return __uint_as_float((bits >> 9) | 0x3f800000u) - 1.0f;
}

__global__ __launch_bounds__(256, 8)
void bayes_kernel(const float* __restrict__ A,
                  const float* __restrict__ Bm,
                  const float* __restrict__ BEVa,
                  const float* __restrict__ BEVb,
                  const int*   __restrict__ kapa,
                  const float* __restrict__ mean,
                  float* __restrict__ out,
                  int S,
                  uint32_t m17, uint32_t m29, uint32_t m16, uint32_t m24) {
    const int b    = blockIdx.x;
    const int tid  = threadIdx.x;
    const int warp = tid >> 5;
    const int lane = tid & 31;
    const int s    = tid;              // warp c covers s in [32c, 32c+32)

    __shared__ float red[8];

    const int kap = kapa[b];

    // Dead warp: publish zero partial, exit (exited threads skip the barrier).
    if ((warp << 5) >= kap) {
        if (lane == 0) red[warp] = 0.0f;
        return;
    }

    // inverse softmax weights (common denominator cancels in the argmin)
    const float m0 = mean[0], m1 = mean[1], m2 = mean[2], m3 = mean[3];
    const float mx = fmaxf(fmaxf(m0, m1), fmaxf(m2, m3));
    const float e0 = __expf(m0 - mx), e1 = __expf(m1 - mx);
    const float e2 = __expf(m2 - mx), e3 = __expf(m3 - mx);
    const float iw[4] = {__fdividef(1.0f, e0), __fdividef(1.0f, e1),
                         __fdividef(1.0f, e2), __fdividef(1.0f, e3)};

    float diff = 0.0f;

    if (s < kap) {
        const uint32_t base = ((uint32_t)b * (uint32_t)S + (uint32_t)s) * 4u;

        float u[4], q[4];
#pragma unroll
        for (int k = 0; k < 4; k++) {
            const uint32_t bits = threefry_xor(base + (uint32_t)k, m17, m29, m16, m24);
            u[k] = bits_to_uniform(bits);
            const float t = -__log2f(u[k]);   // u==0 -> +inf (never wins argmin)
            q[k] = t * iw[k];
        }

        // argmin with runner-up tracking
        int   kb = 0;
        float best = q[0], second = INFINITY;
        if (q[1] < best) { second = best; best = q[1]; kb = 1; } else second = q[1];
        if (q[2] < best) { second = best; best = q[2]; kb = 2; } else if (q[2] < second) second = q[2];
        if (q[3] < best) { second = best; best = q[3]; kb = 3; } else if (q[3] < second) second = q[3];

        if (second - best < best * 1e-3f) {
            // rare accurate fp32 fallback: exact reference formula (with eps)
            const float se  = e0 + e1 + e2 + e3;
            const float lse = mx + logf(se);
            const float lg[4] = {m0 - lse, m1 - lse, m2 - lse, m3 - lse};
            float bs = -INFINITY; int kk = 0;
#pragma unroll
            for (int k = 0; k < 4; k++) {
                const float g  = -logf(-logf(u[k] + EPSF) + EPSF);
                const float sc = lg[k] + g;
                if (sc > bs) { bs = sc; kk = k; }
            }
            kb = kk;
        }

        const float* Ab = A  + (size_t)b * 4 * S;
        const float* Bb = Bm + (size_t)b * 4 * S;
        const size_t off = (size_t)kb * S + s;
        diff = Bb[off] - Ab[off];
    }

    // warp reduction
#pragma unroll
    for (int o = 16; o > 0; o >>= 1)
        diff += __shfl_down_sync(0xffffffffu, diff, o);
    if (lane == 0) red[warp] = diff;

    __syncthreads();

    if (tid == 0) {
        float tot = 0.0f;
#pragma unroll
        for (int wi = 0; wi < 8; wi++) tot += red[wi];
        const float x = BEVb[b] - BEVa[b] + tot / (float)kap;
        out[b] = 1.0f / (1.0f + expf(-x));
    }
}

extern "C" void kernel_launch(void* const* d_in, const int* in_sizes, int n_in,
                              void* d_out, int out_size) {
    // metadata order: outcomeA, outcomeB, BEVa, BEVb, kapa, batch_size, features, mean
    const float* A    = (const float*)d_in[0];
    const float* Bm   = (const float*)d_in[1];
    const float* BEVa = (const float*)d_in[2];
    const float* BEVb = (const float*)d_in[3];
    const int*   kapa = (const int*)  d_in[4];

    // mean is the (only) 4-element input; locate it robustly from the tail
    const float* mean = (const float*)d_in[n_in - 1];
    for (int i = n_in - 1; i >= 5; --i) {
        if (in_sizes[i] == 4) { mean = (const float*)d_in[i]; break; }
    }

    float* out = (float*)d_out;

    const int B = in_sizes[2];                 // 16384
    const int S = in_sizes[0] / (4 * B);       // 256

    bayes_kernel<<<B, 256>>>(A, Bm, BEVa, BEVb, kapa, mean, out, S,
                             1u << 17, 1u << 29, 1u << 16, 1u << 24);
}